// round 15
// baseline (speedup 1.0000x reference)
#include <cuda_runtime.h>
#include <cuda_fp16.h>
#include <math.h>

#define NNODES 50000
#define DEGC 16
// record (104 float words = 416B): y[128 half] | z[64 half] | el[2] er[2] xg2[2] xg1[2] (fp32)
#define RECS 104
#define NT64 782    // 64-node tiles
#define GRID_P2 296 // persistent grid, 2 blocks/SM

// ---------------- scratch (device globals) ---------------------------------
__device__ float g_rec[NNODES * RECS];
__device__ float g_gy[NNODES * 64];
__device__ float g_xm[NNODES * 64];
__device__ float g_vlr[128 * 4];
__device__ float g_U[2 * 128 * 64];

__device__ __forceinline__ float sigmoidf_(float v) { return 1.f / (1.f + __expf(-v)); }

__device__ __forceinline__ void mma_f16(float c[4], unsigned a0, unsigned a1,
                                        unsigned a2, unsigned a3,
                                        unsigned b0, unsigned b1) {
    asm volatile(
        "mma.sync.aligned.m16n8k16.row.col.f32.f16.f16.f32 "
        "{%0,%1,%2,%3}, {%4,%5,%6,%7}, {%8,%9}, {%0,%1,%2,%3};"
        : "+f"(c[0]), "+f"(c[1]), "+f"(c[2]), "+f"(c[3])
        : "r"(a0), "r"(a1), "r"(a2), "r"(a3), "r"(b0), "r"(b1));
}

// k1 smem (floats): wbA 8192 | wbB 8192 | wsc 512 | xa 4096 -> 20992 = 83968 B
#define K1_WBA 0
#define K1_WBB 8192
#define K1_WSC 16384
#define K1_XA  16896
#define K1_SMEM (20992 * 4)
// k3 smem (floats): wbA 7168 | wbB 7168 | ma 2048 | ha 2048 -> 18432 = 73728 B
#define K3_WBA 0
#define K3_WBB 7168
#define K3_MA  14336
#define K3_HA  16384
#define K3_SMEM (18432 * 4)

// ---------------- K0: fold attn vectors + U (one parallel kernel) ----------
__global__ void k0_prep(const float* __restrict__ Wfc,
                        const float* __restrict__ al,
                        const float* __restrict__ ar,
                        const float* __restrict__ Wmerge) {
    int b = blockIdx.x;
    int t = threadIdx.x;  // 64
    if (b < 256) {
        int k = b & 127, h = b >> 7, c = t;
        float s = 0.f;
#pragma unroll 8
        for (int q = 0; q < 64; ++q)
            s += Wfc[k * 128 + h * 64 + q] * Wmerge[(128 + h * 64 + q) * 64 + c];
        g_U[(h * 128 + k) * 64 + c] = s;
    } else {
        for (int o = t; o < 512; o += 64) {
            int k = o >> 2, c = o & 3;
            int h = c & 1;
            const float* av = (c < 2) ? al : ar;
            float s = 0.f;
#pragma unroll 8
            for (int q = 0; q < 64; ++q)
                s += Wfc[k * 128 + h * 64 + q] * av[h * 64 + q];
            g_vlr[o] = s;
        }
    }
}

// fragment-pack helpers (m16n8k16 layouts)
__device__ __forceinline__ int packA_idx(int i16, int kk, int rgKS_plus_ks) {
    int l = ((i16 & 7) << 2) | ((kk & 7) >> 1);
    int j = ((i16 >> 3) << 1) | ((kk >> 3) << 2) | (kk & 1);
    return ((rgKS_plus_ks << 5) + l) * 8 + j;
}

// ---------------- K1 persistent, fp16 mma, 2 blocks/SM ---------------------
__global__ __launch_bounds__(256, 2) void k1_node_linear(
    const float* __restrict__ x, const float* __restrict__ Wm,
    const float* __restrict__ bm, const float* __restrict__ Wg,
    const float* __restrict__ Wmerge) {
    extern __shared__ float sm[];
    float* wbA = sm + K1_WBA;
    float* wbB = sm + K1_WBB;
    float* wsc = sm + K1_WSC;
    float* xa  = sm + K1_XA;
    __half* wbA_h = (__half*)wbA;
    __half* wbB_h = (__half*)wbB;
    __half* wsc_h = (__half*)wsc;
    __half* xa_h  = (__half*)xa;
    const int tid = threadIdx.x, lane = tid & 31, wid = tid >> 5;
    const int rg = wid >> 1;           // rowgroup 0..3 (64 rows)
    const int ch = wid & 1;
    const int row0 = rg * 16 + (lane >> 2);
    const int colh = ch * 32;

    // ---- pack weights (once per block) ----
    for (int idx = tid; idx < 4 * 128 * 64; idx += 256) {
        int p = idx >> 13, rem = idx & 8191, k = rem >> 6, c = rem & 63;
        float w;
        if (p == 0) w = Wm[k * 64 + c];
        else if (p == 3) w = Wmerge[k * 64 + c];
        else w = g_U[((p - 1) * 128 + k) * 64 + c];
        int cch = c >> 5, cc = c & 31, nt = cc >> 3, cl = cc & 7;
        int ks = k >> 4, kk = k & 15;
        int l = (cl << 2) | ((kk & 7) >> 1);
        int hlf = ((nt & 1) << 2) | ((kk >> 3) << 1) | (kk & 1);
        int slot = p * 2 + cch;
        __half hv = __float2half(w);
        int pi = (((slot * 8 + ks) << 5) + l) * 8 + hlf;
        if (nt >> 1) wbB_h[pi] = hv; else wbA_h[pi] = hv;
    }
    // scalar weights: 8 cols per k
    for (int idx = tid; idx < 128 * 8; idx += 256) {
        int k = idx >> 3, c = idx & 7;
        float v;
        if (c < 4) v = g_vlr[k * 4 + c];
        else if (c < 6) v = Wg[(128 + k) * 2 + (c - 4)];
        else v = Wg[k * 2 + (c - 6)];
        int ks = k >> 4, kk = k & 15;
        int l = (c << 2) | ((kk & 7) >> 1);
        int hlf = ((kk >> 3) << 1) | (kk & 1);
        wsc_h[(((ks) << 5) + l) * 4 + hlf] = __float2half(v);
    }

    for (int t = blockIdx.x; t < NT64; t += GRID_P2) {
        const int n0 = t * 64;
        __syncthreads();  // prior readers done / weights packed
        for (int idx = tid; idx < 64 * 128; idx += 256) {
            int nn = idx >> 7, k = idx & 127;
            int node = n0 + nn;
            float v = (node < NNODES) ? x[node * 128 + k] : 0.f;
            xa_h[packA_idx(nn & 15, k & 15, (nn >> 4) * 8 + (k >> 4))] = __float2half(v);
        }
        __syncthreads();

        float C[4][4][4];   // [pass][nt][e]
        float Cs[4];
#pragma unroll
        for (int p = 0; p < 4; ++p)
#pragma unroll
            for (int nt = 0; nt < 4; ++nt)
#pragma unroll
                for (int e = 0; e < 4; ++e) C[p][nt][e] = 0.f;
#pragma unroll
        for (int e = 0; e < 4; ++e) Cs[e] = 0.f;

#pragma unroll
        for (int ks = 0; ks < 8; ++ks) {
            uint4 av = ((const uint4*)xa)[(rg * 8 + ks) * 32 + lane];
#pragma unroll
            for (int p = 0; p < 4; ++p) {
                int s = p * 2 + ch;
                uint4 b01 = ((const uint4*)wbA)[(s * 8 + ks) * 32 + lane];
                uint4 b23 = ((const uint4*)wbB)[(s * 8 + ks) * 32 + lane];
                mma_f16(C[p][0], av.x, av.y, av.z, av.w, b01.x, b01.y);
                mma_f16(C[p][1], av.x, av.y, av.z, av.w, b01.z, b01.w);
                mma_f16(C[p][2], av.x, av.y, av.z, av.w, b23.x, b23.y);
                mma_f16(C[p][3], av.x, av.y, av.z, av.w, b23.z, b23.w);
            }
            if (ch == 0) {
                uint2 sb = ((const uint2*)wsc)[ks * 32 + lane];
                mma_f16(Cs, av.x, av.y, av.z, av.w, sb.x, sb.y);
            }
        }

        const int node0 = n0 + row0, node1 = node0 + 8;
        // p=0: z -> fp16 at word offset 64 (with bias)
#pragma unroll
        for (int nt = 0; nt < 4; ++nt) {
            int c0 = colh + nt * 8 + (lane & 3) * 2;
            float ba = bm[c0], bb = bm[c0 + 1];
            if (node0 < NNODES)
                ((__half2*)(g_rec + (size_t)node0 * RECS + 64))[c0 >> 1] =
                    __floats2half2_rn(C[0][nt][0] + ba, C[0][nt][1] + bb);
            if (node1 < NNODES)
                ((__half2*)(g_rec + (size_t)node1 * RECS + 64))[c0 >> 1] =
                    __floats2half2_rn(C[0][nt][2] + ba, C[0][nt][3] + bb);
        }
        // p=1,2: y heads -> fp16 at word offset 0
#pragma unroll
        for (int p = 1; p <= 2; ++p) {
#pragma unroll
            for (int nt = 0; nt < 4; ++nt) {
                int c0 = colh + nt * 8 + (lane & 3) * 2;
                int hb = (p - 1) * 64 + c0;
                if (node0 < NNODES)
                    ((__half2*)(g_rec + (size_t)node0 * RECS))[hb >> 1] =
                        __floats2half2_rn(C[p][nt][0], C[p][nt][1]);
                if (node1 < NNODES)
                    ((__half2*)(g_rec + (size_t)node1 * RECS))[hb >> 1] =
                        __floats2half2_rn(C[p][nt][2], C[p][nt][3]);
            }
        }
        // p=3: xm fp32
#pragma unroll
        for (int nt = 0; nt < 4; ++nt) {
            int c0 = colh + nt * 8 + (lane & 3) * 2;
            if (node0 < NNODES)
                *(float2*)&g_xm[(size_t)node0 * 64 + c0] =
                    make_float2(C[3][nt][0], C[3][nt][1]);
            if (node1 < NNODES)
                *(float2*)&g_xm[(size_t)node1 * 64 + c0] =
                    make_float2(C[3][nt][2], C[3][nt][3]);
        }
        // scalars fp32 at word offset 96
        if (ch == 0) {
            int c0 = (lane & 3) * 2;
            if (node0 < NNODES)
                *(float2*)&g_rec[(size_t)node0 * RECS + 96 + c0] =
                    make_float2(Cs[0], Cs[1]);
            if (node1 < NNODES)
                *(float2*)&g_rec[(size_t)node1 * RECS + 96 + c0] =
                    make_float2(Cs[2], Cs[3]);
        }
    }
}

// ---------------- K2: one warp per node, fp16 gathers ----------------------
__global__ __launch_bounds__(256) void k2_aggregate(
    const int* __restrict__ src, const float* __restrict__ Wg,
    const float* __restrict__ bg) {
    const unsigned FULL = 0xffffffffu;
    const int n = blockIdx.x * 8 + ((threadIdx.x) >> 5);
    if (n >= NNODES) return;
    const int lane = threadIdx.x & 31;
    const int j16 = lane & 15, h = lane >> 4;

    int srcj = src[n * DEGC + j16];

    float el = g_rec[(size_t)srcj * RECS + 96 + h];
    float er = g_rec[(size_t)n * RECS + 98 + h];
    float e = el + er;
    e = (e > 0.f) ? e : 0.2f * e;
    float m = e;
#pragma unroll
    for (int o = 8; o > 0; o >>= 1) m = fmaxf(m, __shfl_xor_sync(FULL, m, o));
    float ee = __expf(e - m);
    float s = ee;
#pragma unroll
    for (int o = 8; o > 0; o >>= 1) s += __shfl_xor_sync(FULL, s, o);
    float alpha = ee / fmaxf(s, 1e-12f);

    float xg2 = g_rec[(size_t)srcj * RECS + 100 + h];
#pragma unroll
    for (int o = 8; o > 0; o >>= 1) xg2 += __shfl_xor_sync(FULL, xg2, o);

    float mz0 = -3.4e38f, mz1 = -3.4e38f;
#pragma unroll
    for (int j = 0; j < 16; ++j) {
        int sj = __shfl_sync(FULL, srcj, j);
        unsigned zv = *(const unsigned*)(g_rec + (size_t)sj * RECS + 64 + lane);
        float2 z2 = __half22float2(*(__half2*)&zv);
        mz0 = fmaxf(mz0, z2.x);
        mz1 = fmaxf(mz1, z2.y);
    }
    float p0 = mz0 * Wg[(256 + 2 * lane) * 2 + 0] + mz1 * Wg[(256 + 2 * lane + 1) * 2 + 0];
    float p1 = mz0 * Wg[(256 + 2 * lane) * 2 + 1] + mz1 * Wg[(256 + 2 * lane + 1) * 2 + 1];
#pragma unroll
    for (int o = 16; o > 0; o >>= 1) {
        p0 += __shfl_xor_sync(FULL, p0, o);
        p1 += __shfl_xor_sync(FULL, p1, o);
    }
    float g3 = (h == 0) ? p0 : p1;
    float xg1 = g_rec[(size_t)n * RECS + 102 + h];
    float gate = sigmoidf_(xg1 + 0.0625f * xg2 + g3 + bg[h]);

    float4 acc = make_float4(0.f, 0.f, 0.f, 0.f);
#pragma unroll
    for (int j = 0; j < 16; ++j) {
        int sj = __shfl_sync(FULL, srcj, j);
        float a = __shfl_sync(FULL, alpha, (lane & 16) | j);
        uint2 yv = *(const uint2*)(g_rec + (size_t)sj * RECS + 2 * lane);
        float2 f0 = __half22float2(*(__half2*)&yv.x);
        float2 f1 = __half22float2(*(__half2*)&yv.y);
        acc.x += a * f0.x; acc.y += a * f0.y;
        acc.z += a * f1.x; acc.w += a * f1.y;
    }

    float got = __shfl_xor_sync(FULL, gate, 16);
    float ox = __shfl_xor_sync(FULL, acc.x, 16);
    float oy = __shfl_xor_sync(FULL, acc.y, 16);
    float oz = __shfl_xor_sync(FULL, acc.z, 16);
    float ow = __shfl_xor_sync(FULL, acc.w, 16);
    if (lane < 16) {
        float4 gy;
        gy.x = gate * acc.x + got * ox;
        gy.y = gate * acc.y + got * oy;
        gy.z = gate * acc.z + got * oz;
        gy.w = gate * acc.w + got * ow;
        *(float4*)&g_gy[(size_t)n * 64 + 4 * lane] = gy;
    }
}

// ---------------- K3 persistent, fp16 mma, 2 blocks/SM ---------------------
__global__ __launch_bounds__(256, 2) void k3_fused(
    const float* __restrict__ bmerge,
    const float* __restrict__ hin, const float* __restrict__ W_ih,
    const float* __restrict__ W_hh, const float* __restrict__ b_ih,
    const float* __restrict__ b_hh, const float* __restrict__ Wout,
    const float* __restrict__ bout, float* __restrict__ out) {
    extern __shared__ float sm[];
    float* wbA = sm + K3_WBA;
    float* wbB = sm + K3_WBB;
    float* ma  = sm + K3_MA;   // meso packed; aliased by nh after g==2 (fenced)
    float* ha  = sm + K3_HA;   // hidden packed (fp16)
    __half* wbA_h = (__half*)wbA;
    __half* wbB_h = (__half*)wbB;
    __half* ma_h  = (__half*)ma;
    __half* ha_h  = (__half*)ha;
    const int tid = threadIdx.x, lane = tid & 31, wid = tid >> 5;
    const int rg = wid >> 1;   // 0..3 (64 rows)
    const int ch = wid & 1;
    const int row0 = rg * 16 + (lane >> 2);
    const int colh = ch * 32;

    // ---- pack 7 weight matrices: 0..2 W_ih, 3..5 W_hh, 6 Wout ----
    for (int idx = tid; idx < 7 * 64 * 64; idx += 256) {
        int mm = idx >> 12, rem = idx & 4095, k = rem >> 6, c = rem & 63;
        float w;
        if (mm < 3) w = W_ih[(mm * 64 + c) * 64 + k];
        else if (mm < 6) w = W_hh[((mm - 3) * 64 + c) * 64 + k];
        else w = Wout[k * 64 + c];
        int cch = c >> 5, cc = c & 31, nt = cc >> 3, cl = cc & 7;
        int ks = k >> 4, kk = k & 15;
        int l = (cl << 2) | ((kk & 7) >> 1);
        int hlf = ((nt & 1) << 2) | ((kk >> 3) << 1) | (kk & 1);
        int slot = mm * 2 + cch;
        int pi = (((slot * 4 + ks) << 5) + l) * 8 + hlf;
        __half hv = __float2half(w);
        if (nt >> 1) wbB_h[pi] = hv; else wbA_h[pi] = hv;
    }

    for (int t = blockIdx.x; t < NT64; t += GRID_P2) {
        const int n0 = t * 64;
        const int node0 = n0 + row0, node1 = node0 + 8;
        __syncthreads();  // prior tile readers done / weights packed

        // fill ms (= xm + gy + bmerge) and h tile, fragment-packed fp16
        for (int idx = tid; idx < 64 * 64; idx += 256) {
            int nn = idx >> 6, k = idx & 63;
            int node = n0 + nn;
            float mv = 0.f, hv = 0.f;
            if (node < NNODES) {
                mv = g_xm[(size_t)node * 64 + k] + g_gy[(size_t)node * 64 + k] + bmerge[k];
                hv = hin[node * 64 + k];
            }
            int pi = packA_idx(nn & 15, k & 15, (nn >> 4) * 4 + (k >> 4));
            ma_h[pi] = __float2half(mv);
            ha_h[pi] = __float2half(hv);
        }
        __syncthreads();

        float rr[4][4], zz[4][4];
#pragma unroll
        for (int g = 0; g < 3; ++g) {
            float ai[4][4], ah[4][4];
#pragma unroll
            for (int nt = 0; nt < 4; ++nt)
#pragma unroll
                for (int e = 0; e < 4; ++e) { ai[nt][e] = 0.f; ah[nt][e] = 0.f; }
#pragma unroll
            for (int ks = 0; ks < 4; ++ks) {
                uint4 av = ((const uint4*)ma)[(rg * 4 + ks) * 32 + lane];
                uint4 hv4 = ((const uint4*)ha)[(rg * 4 + ks) * 32 + lane];
                int si = (g * 2 + ch) * 4 + ks;
                int sh = ((3 + g) * 2 + ch) * 4 + ks;
                uint4 wi01 = ((const uint4*)wbA)[si * 32 + lane];
                uint4 wi23 = ((const uint4*)wbB)[si * 32 + lane];
                uint4 wh01 = ((const uint4*)wbA)[sh * 32 + lane];
                uint4 wh23 = ((const uint4*)wbB)[sh * 32 + lane];
                mma_f16(ai[0], av.x, av.y, av.z, av.w, wi01.x, wi01.y);
                mma_f16(ai[1], av.x, av.y, av.z, av.w, wi01.z, wi01.w);
                mma_f16(ai[2], av.x, av.y, av.z, av.w, wi23.x, wi23.y);
                mma_f16(ai[3], av.x, av.y, av.z, av.w, wi23.z, wi23.w);
                mma_f16(ah[0], hv4.x, hv4.y, hv4.z, hv4.w, wh01.x, wh01.y);
                mma_f16(ah[1], hv4.x, hv4.y, hv4.z, hv4.w, wh01.z, wh01.w);
                mma_f16(ah[2], hv4.x, hv4.y, hv4.z, hv4.w, wh23.x, wh23.y);
                mma_f16(ah[3], hv4.x, hv4.y, hv4.z, hv4.w, wh23.z, wh23.w);
            }

            if (g == 2) __syncthreads();  // all ma reads done before nh overwrite

#pragma unroll
            for (int nt = 0; nt < 4; ++nt) {
#pragma unroll
                for (int half = 0; half < 2; ++half) {
                    int e0 = half * 2;
                    int c0 = colh + nt * 8 + (lane & 3) * 2;
                    int r = row0 + half * 8;
                    if (g == 0) {
                        rr[nt][e0]     = sigmoidf_(ai[nt][e0] + b_ih[c0] +
                                                   ah[nt][e0] + b_hh[c0]);
                        rr[nt][e0 + 1] = sigmoidf_(ai[nt][e0 + 1] + b_ih[c0 + 1] +
                                                   ah[nt][e0 + 1] + b_hh[c0 + 1]);
                    } else if (g == 1) {
                        zz[nt][e0]     = sigmoidf_(ai[nt][e0] + b_ih[64 + c0] +
                                                   ah[nt][e0] + b_hh[64 + c0]);
                        zz[nt][e0 + 1] = sigmoidf_(ai[nt][e0 + 1] + b_ih[64 + c0 + 1] +
                                                   ah[nt][e0 + 1] + b_hh[64 + c0 + 1]);
                    } else {
                        float v[2];
#pragma unroll
                        for (int q = 0; q < 2; ++q) {
                            int c = c0 + q;
                            float gi = ai[nt][e0 + q] + b_ih[128 + c];
                            float gh = ah[nt][e0 + q] + b_hh[128 + c];
                            float ng = tanhf(gi + rr[nt][e0 + q] * gh);
                            int l = ((lane >> 2) << 2) | ((c & 7) >> 1);
                            int j = (half << 1) | (((c >> 3) & 1) << 2) | (c & 1);
                            int pi = (((rg * 4 + (c >> 4)) * 32 + l) << 3) + j;
                            float hvv = __half2float(ha_h[pi]);
                            v[q] = (1.f - zz[nt][e0 + q]) * ng + zz[nt][e0 + q] * hvv;
                            ma_h[pi] = __float2half(v[q]);  // nh packed
                        }
                        int node = n0 + r;
                        if (node < NNODES)
                            *(float2*)&out[(size_t)NNODES * 64 + (size_t)node * 64 + c0] =
                                make_float2(v[0], v[1]);
                    }
                }
            }
        }
        __syncthreads();  // nh complete

        // output projection: source = nh @ Wout + bout
        float C[4][4];
#pragma unroll
        for (int nt = 0; nt < 4; ++nt)
#pragma unroll
            for (int e = 0; e < 4; ++e) C[nt][e] = 0.f;
#pragma unroll
        for (int ks = 0; ks < 4; ++ks) {
            uint4 av = ((const uint4*)ma)[(rg * 4 + ks) * 32 + lane];
            int s = (6 * 2 + ch) * 4 + ks;
            uint4 b01 = ((const uint4*)wbA)[s * 32 + lane];
            uint4 b23 = ((const uint4*)wbB)[s * 32 + lane];
            mma_f16(C[0], av.x, av.y, av.z, av.w, b01.x, b01.y);
            mma_f16(C[1], av.x, av.y, av.z, av.w, b01.z, b01.w);
            mma_f16(C[2], av.x, av.y, av.z, av.w, b23.x, b23.y);
            mma_f16(C[3], av.x, av.y, av.z, av.w, b23.z, b23.w);
        }
#pragma unroll
        for (int nt = 0; nt < 4; ++nt) {
            int c0 = colh + nt * 8 + (lane & 3) * 2;
            float ba = bout[c0], bb = bout[c0 + 1];
            if (node0 < NNODES)
                *(float2*)&out[(size_t)node0 * 64 + c0] =
                    make_float2(C[nt][0] + ba, C[nt][1] + bb);
            if (node1 < NNODES)
                *(float2*)&out[(size_t)node1 * 64 + c0] =
                    make_float2(C[nt][2] + ba, C[nt][3] + bb);
        }
    }
}

// ---------------- launch ---------------------------------------------------
extern "C" void kernel_launch(void* const* d_in, const int* in_sizes, int n_in,
                              void* d_out, int out_size) {
    const float* x    = (const float*)d_in[0];
    const float* hin  = (const float*)d_in[1];
    const int*   srcp = (const int*)d_in[2];
    const float* Wm   = (const float*)d_in[4];
    const float* bm   = (const float*)d_in[5];
    const float* Wg   = (const float*)d_in[6];
    const float* bg   = (const float*)d_in[7];
    const float* Wfc  = (const float*)d_in[8];
    const float* al   = (const float*)d_in[9];
    const float* ar   = (const float*)d_in[10];
    const float* Wmg  = (const float*)d_in[11];
    const float* bmg  = (const float*)d_in[12];
    const float* Wih  = (const float*)d_in[13];
    const float* Whh  = (const float*)d_in[14];
    const float* bih  = (const float*)d_in[15];
    const float* bhh  = (const float*)d_in[16];
    const float* Wo   = (const float*)d_in[17];
    const float* bo   = (const float*)d_in[18];
    float* out = (float*)d_out;

    cudaFuncSetAttribute(k1_node_linear, cudaFuncAttributeMaxDynamicSharedMemorySize, K1_SMEM);
    cudaFuncSetAttribute(k3_fused, cudaFuncAttributeMaxDynamicSharedMemorySize, K3_SMEM);

    k0_prep<<<257, 64>>>(Wfc, al, ar, Wmg);
    k1_node_linear<<<GRID_P2, 256, K1_SMEM>>>(x, Wm, bm, Wg, Wmg);
    k2_aggregate<<<(NNODES + 7) / 8, 256>>>(srcp, Wg, bg);
    k3_fused<<<GRID_P2, 256, K3_SMEM>>>(bmg, hin, Wih, Whh, bih, bhh, Wo, bo, out);
}

// round 17
// speedup vs baseline: 1.3482x; 1.3482x over previous
#include <cuda_runtime.h>
#include <cuda_fp16.h>
#include <math.h>

#define NNODES 50000
#define DEGC 16
// record (104 float words = 416B): y[128 half] | z[64 half] | el[2] er[2] xg2[2] xg1[2] (fp32)
#define RECS 104
#define NT64 782
#define GRID_P2 296 // 2 blocks/SM

// ---------------- scratch (device globals) ---------------------------------
__device__ float g_rec[NNODES * RECS];
__device__ float g_xm[NNODES * 64];
__device__ float g_vlr[128 * 4];
__device__ float g_U[2 * 128 * 64];
// pre-packed fragment weights (fp16)
__device__ __align__(16) __half g_k1wbA[16384];
__device__ __align__(16) __half g_k1wbB[16384];
__device__ __align__(16) __half g_k1wsc[1024];
__device__ __align__(16) __half g_k3wbA[14336];
__device__ __align__(16) __half g_k3wbB[14336];

__device__ __forceinline__ float sigmoidf_(float v) { return 1.f / (1.f + __expf(-v)); }

__device__ __forceinline__ void mma_f16(float c[4], unsigned a0, unsigned a1,
                                        unsigned a2, unsigned a3,
                                        unsigned b0, unsigned b1) {
    asm volatile(
        "mma.sync.aligned.m16n8k16.row.col.f32.f16.f16.f32 "
        "{%0,%1,%2,%3}, {%4,%5,%6,%7}, {%8,%9}, {%0,%1,%2,%3};"
        : "+f"(c[0]), "+f"(c[1]), "+f"(c[2]), "+f"(c[3])
        : "r"(a0), "r"(a1), "r"(a2), "r"(a3), "r"(b0), "r"(b1));
}

// k1 smem (floats): wbA 8192 | wbB 8192 | wsc 512 | xa 4096 -> 20992 = 83968 B
#define K1_WBA 0
#define K1_WBB 8192
#define K1_WSC 16384
#define K1_XA  16896
#define K1_SMEM (20992 * 4)
// k3 smem (floats): wbA 7168 | wbB 7168 | ma 2048 | ha 2048 | gy 4096 -> 22528 = 90112 B
#define K3_WBA 0
#define K3_WBB 7168
#define K3_MA  14336
#define K3_HA  16384
#define K3_GY  18432
#define K3_SMEM (22528 * 4)

// ---------------- K0a: fold attn vectors + U -------------------------------
__global__ void k0_prep(const float* __restrict__ Wfc,
                        const float* __restrict__ al,
                        const float* __restrict__ ar,
                        const float* __restrict__ Wmerge) {
    int b = blockIdx.x;
    int t = threadIdx.x;  // 64
    if (b < 256) {
        int k = b & 127, h = b >> 7, c = t;
        float s = 0.f;
#pragma unroll 8
        for (int q = 0; q < 64; ++q)
            s += Wfc[k * 128 + h * 64 + q] * Wmerge[(128 + h * 64 + q) * 64 + c];
        g_U[(h * 128 + k) * 64 + c] = s;
    } else {
        for (int o = t; o < 512; o += 64) {
            int k = o >> 2, c = o & 3;
            int h = c & 1;
            const float* av = (c < 2) ? al : ar;
            float s = 0.f;
#pragma unroll 8
            for (int q = 0; q < 64; ++q)
                s += Wfc[k * 128 + h * 64 + q] * av[h * 64 + q];
            g_vlr[o] = s;
        }
    }
}

// ---------------- K0b: pack all weights into fragment layout (once) --------
__global__ void k0_pack(const float* __restrict__ Wm, const float* __restrict__ Wg,
                        const float* __restrict__ Wmerge,
                        const float* __restrict__ W_ih, const float* __restrict__ W_hh,
                        const float* __restrict__ Wout) {
    int idx = blockIdx.x * 256 + threadIdx.x;
    if (idx < 32768) {
        // k1 main: p 0..3, k 0..127, c 0..63
        int p = idx >> 13, rem = idx & 8191, k = rem >> 6, c = rem & 63;
        float w;
        if (p == 0) w = Wm[k * 64 + c];
        else if (p == 3) w = Wmerge[k * 64 + c];
        else w = g_U[((p - 1) * 128 + k) * 64 + c];
        int cch = c >> 5, cc = c & 31, nt = cc >> 3, cl = cc & 7;
        int ks = k >> 4, kk = k & 15;
        int l = (cl << 2) | ((kk & 7) >> 1);
        int hlf = ((nt & 1) << 2) | ((kk >> 3) << 1) | (kk & 1);
        int slot = p * 2 + cch;
        int pi = (((slot * 8 + ks) << 5) + l) * 8 + hlf;
        __half hv = __float2half(w);
        if (nt >> 1) g_k1wbB[pi] = hv; else g_k1wbA[pi] = hv;
    } else if (idx < 33792) {
        int i = idx - 32768;
        int k = i >> 3, c = i & 7;
        float v;
        if (c < 4) v = g_vlr[k * 4 + c];
        else if (c < 6) v = Wg[(128 + k) * 2 + (c - 4)];
        else v = Wg[k * 2 + (c - 6)];
        int ks = k >> 4, kk = k & 15;
        int l = (c << 2) | ((kk & 7) >> 1);
        int hlf = ((kk >> 3) << 1) | (kk & 1);
        g_k1wsc[(((ks) << 5) + l) * 4 + hlf] = __float2half(v);
    } else if (idx < 33792 + 28672) {
        int i = idx - 33792;
        int mm = i >> 12, rem = i & 4095, k = rem >> 6, c = rem & 63;
        float w;
        if (mm < 3) w = W_ih[(mm * 64 + c) * 64 + k];
        else if (mm < 6) w = W_hh[((mm - 3) * 64 + c) * 64 + k];
        else w = Wout[k * 64 + c];
        int cch = c >> 5, cc = c & 31, nt = cc >> 3, cl = cc & 7;
        int ks = k >> 4, kk = k & 15;
        int l = (cl << 2) | ((kk & 7) >> 1);
        int hlf = ((nt & 1) << 2) | ((kk >> 3) << 1) | (kk & 1);
        int slot = mm * 2 + cch;
        int pi = (((slot * 4 + ks) << 5) + l) * 8 + hlf;
        __half hv = __float2half(w);
        if (nt >> 1) g_k3wbB[pi] = hv; else g_k3wbA[pi] = hv;
    }
}

// fragment-pack helper (m16n8k16 A layout)
__device__ __forceinline__ int packA_idx(int i16, int kk, int rgKS) {
    int l = ((i16 & 7) << 2) | ((kk & 7) >> 1);
    int j = ((i16 >> 3) << 1) | ((kk >> 3) << 2) | (kk & 1);
    return ((rgKS << 5) + l) * 8 + j;
}

// ---------------- K1 persistent, fp16 mma, linear weight copy --------------
__global__ __launch_bounds__(256, 2) void k1_node_linear(
    const float* __restrict__ x, const float* __restrict__ bm) {
    extern __shared__ float sm[];
    float* wbA = sm + K1_WBA;
    float* wbB = sm + K1_WBB;
    float* wsc = sm + K1_WSC;
    float* xa  = sm + K1_XA;
    __half* xa_h = (__half*)xa;
    const int tid = threadIdx.x, lane = tid & 31, wid = tid >> 5;
    const int rg = wid >> 1;   // 0..3
    const int ch = wid & 1;
    const int row0 = rg * 16 + (lane >> 2);
    const int colh = ch * 32;

    // linear vectorized weight copy (pre-packed)
    {
        const uint4* sA = (const uint4*)g_k1wbA;
        const uint4* sB = (const uint4*)g_k1wbB;
        const uint4* sC = (const uint4*)g_k1wsc;
        uint4* dA = (uint4*)wbA;
        uint4* dB = (uint4*)wbB;
        uint4* dC = (uint4*)wsc;
        for (int i = tid; i < 2048; i += 256) { dA[i] = sA[i]; dB[i] = sB[i]; }
        for (int i = tid; i < 128; i += 256) dC[i] = sC[i];
    }

    for (int t = blockIdx.x; t < NT64; t += GRID_P2) {
        const int n0 = t * 64;
        __syncthreads();  // prior readers done / weights copied
        for (int idx = tid; idx < 64 * 128; idx += 256) {
            int nn = idx >> 7, k = idx & 127;
            int node = n0 + nn;
            float v = (node < NNODES) ? x[node * 128 + k] : 0.f;
            xa_h[packA_idx(nn & 15, k & 15, (nn >> 4) * 8 + (k >> 4))] = __float2half(v);
        }
        __syncthreads();

        float C[4][4][4];
        float Cs[4];
#pragma unroll
        for (int p = 0; p < 4; ++p)
#pragma unroll
            for (int nt = 0; nt < 4; ++nt)
#pragma unroll
                for (int e = 0; e < 4; ++e) C[p][nt][e] = 0.f;
#pragma unroll
        for (int e = 0; e < 4; ++e) Cs[e] = 0.f;

#pragma unroll
        for (int ks = 0; ks < 8; ++ks) {
            uint4 av = ((const uint4*)xa)[(rg * 8 + ks) * 32 + lane];
#pragma unroll
            for (int p = 0; p < 4; ++p) {
                int s = p * 2 + ch;
                uint4 b01 = ((const uint4*)wbA)[(s * 8 + ks) * 32 + lane];
                uint4 b23 = ((const uint4*)wbB)[(s * 8 + ks) * 32 + lane];
                mma_f16(C[p][0], av.x, av.y, av.z, av.w, b01.x, b01.y);
                mma_f16(C[p][1], av.x, av.y, av.z, av.w, b01.z, b01.w);
                mma_f16(C[p][2], av.x, av.y, av.z, av.w, b23.x, b23.y);
                mma_f16(C[p][3], av.x, av.y, av.z, av.w, b23.z, b23.w);
            }
            if (ch == 0) {
                uint2 sb = ((const uint2*)wsc)[ks * 32 + lane];
                mma_f16(Cs, av.x, av.y, av.z, av.w, sb.x, sb.y);
            }
        }

        const int node0 = n0 + row0, node1 = node0 + 8;
#pragma unroll
        for (int nt = 0; nt < 4; ++nt) {
            int c0 = colh + nt * 8 + (lane & 3) * 2;
            float ba = bm[c0], bb = bm[c0 + 1];
            if (node0 < NNODES)
                ((__half2*)(g_rec + (size_t)node0 * RECS + 64))[c0 >> 1] =
                    __floats2half2_rn(C[0][nt][0] + ba, C[0][nt][1] + bb);
            if (node1 < NNODES)
                ((__half2*)(g_rec + (size_t)node1 * RECS + 64))[c0 >> 1] =
                    __floats2half2_rn(C[0][nt][2] + ba, C[0][nt][3] + bb);
        }
#pragma unroll
        for (int p = 1; p <= 2; ++p) {
#pragma unroll
            for (int nt = 0; nt < 4; ++nt) {
                int c0 = colh + nt * 8 + (lane & 3) * 2;
                int hb = (p - 1) * 64 + c0;
                if (node0 < NNODES)
                    ((__half2*)(g_rec + (size_t)node0 * RECS))[hb >> 1] =
                        __floats2half2_rn(C[p][nt][0], C[p][nt][1]);
                if (node1 < NNODES)
                    ((__half2*)(g_rec + (size_t)node1 * RECS))[hb >> 1] =
                        __floats2half2_rn(C[p][nt][2], C[p][nt][3]);
            }
        }
#pragma unroll
        for (int nt = 0; nt < 4; ++nt) {
            int c0 = colh + nt * 8 + (lane & 3) * 2;
            if (node0 < NNODES)
                *(float2*)&g_xm[(size_t)node0 * 64 + c0] =
                    make_float2(C[3][nt][0], C[3][nt][1]);
            if (node1 < NNODES)
                *(float2*)&g_xm[(size_t)node1 * 64 + c0] =
                    make_float2(C[3][nt][2], C[3][nt][3]);
        }
        if (ch == 0) {
            int c0 = (lane & 3) * 2;
            if (node0 < NNODES)
                *(float2*)&g_rec[(size_t)node0 * RECS + 96 + c0] =
                    make_float2(Cs[0], Cs[1]);
            if (node1 < NNODES)
                *(float2*)&g_rec[(size_t)node1 * RECS + 96 + c0] =
                    make_float2(Cs[2], Cs[3]);
        }
    }
}

// ---------------- K3 fused: gather/softmax/gate prologue + GRU + out -------
__global__ __launch_bounds__(256, 2) void k3_fused(
    const int* __restrict__ src, const float* __restrict__ Wg,
    const float* __restrict__ bg, const float* __restrict__ bmerge,
    const float* __restrict__ hin, const float* __restrict__ b_ih,
    const float* __restrict__ b_hh, const float* __restrict__ bout,
    float* __restrict__ out) {
    extern __shared__ float sm[];
    float* wbA = sm + K3_WBA;
    float* wbB = sm + K3_WBB;
    float* ma  = sm + K3_MA;   // meso packed; aliased by nh after g==2 (fenced)
    float* ha  = sm + K3_HA;
    float* gys = sm + K3_GY;   // [64][64] fp32 gate-weighted attn
    __half* ma_h = (__half*)ma;
    __half* ha_h = (__half*)ha;
    const unsigned FULL = 0xffffffffu;
    const int tid = threadIdx.x, lane = tid & 31, wid = tid >> 5;
    const int rg = wid >> 1;
    const int ch = wid & 1;
    const int row0 = rg * 16 + (lane >> 2);
    const int colh = ch * 32;

    // linear vectorized weight copy (pre-packed)
    {
        const uint4* sA = (const uint4*)g_k3wbA;
        const uint4* sB = (const uint4*)g_k3wbB;
        uint4* dA = (uint4*)wbA;
        uint4* dB = (uint4*)wbB;
        for (int i = tid; i < 1792; i += 256) { dA[i] = sA[i]; dB[i] = sB[i]; }
    }

    for (int t = blockIdx.x; t < NT64; t += GRID_P2) {
        const int n0 = t * 64;
        const int node0 = n0 + row0, node1 = node0 + 8;
        __syncthreads();  // prior tile readers done / weights copied

        // ---- prologue: k2 logic, 8 nodes per warp, gy -> smem --------------
        const int j16 = lane & 15, hh = lane >> 4;
#pragma unroll 1
        for (int q = 0; q < 8; ++q) {
            int n = n0 + wid * 8 + q;
            if (n < NNODES) {
                int srcj = src[n * DEGC + j16];
                float el = g_rec[(size_t)srcj * RECS + 96 + hh];
                float er = g_rec[(size_t)n * RECS + 98 + hh];
                float e = el + er;
                e = (e > 0.f) ? e : 0.2f * e;
                float m = e;
#pragma unroll
                for (int o = 8; o > 0; o >>= 1) m = fmaxf(m, __shfl_xor_sync(FULL, m, o));
                float ee = __expf(e - m);
                float s = ee;
#pragma unroll
                for (int o = 8; o > 0; o >>= 1) s += __shfl_xor_sync(FULL, s, o);
                float alpha = ee / fmaxf(s, 1e-12f);

                float xg2 = g_rec[(size_t)srcj * RECS + 100 + hh];
#pragma unroll
                for (int o = 8; o > 0; o >>= 1) xg2 += __shfl_xor_sync(FULL, xg2, o);

                float mz0 = -3.4e38f, mz1 = -3.4e38f;
#pragma unroll
                for (int j = 0; j < 16; ++j) {
                    int sj = __shfl_sync(FULL, srcj, j);
                    unsigned zv = *(const unsigned*)(g_rec + (size_t)sj * RECS + 64 + lane);
                    float2 z2 = __half22float2(*(__half2*)&zv);
                    mz0 = fmaxf(mz0, z2.x);
                    mz1 = fmaxf(mz1, z2.y);
                }
                float p0 = mz0 * Wg[(256 + 2 * lane) * 2 + 0] +
                           mz1 * Wg[(256 + 2 * lane + 1) * 2 + 0];
                float p1 = mz0 * Wg[(256 + 2 * lane) * 2 + 1] +
                           mz1 * Wg[(256 + 2 * lane + 1) * 2 + 1];
#pragma unroll
                for (int o = 16; o > 0; o >>= 1) {
                    p0 += __shfl_xor_sync(FULL, p0, o);
                    p1 += __shfl_xor_sync(FULL, p1, o);
                }
                float g3 = (hh == 0) ? p0 : p1;
                float xg1 = g_rec[(size_t)n * RECS + 102 + hh];
                float gate = sigmoidf_(xg1 + 0.0625f * xg2 + g3 + bg[hh]);

                float4 acc = make_float4(0.f, 0.f, 0.f, 0.f);
#pragma unroll
                for (int j = 0; j < 16; ++j) {
                    int sj = __shfl_sync(FULL, srcj, j);
                    float a = __shfl_sync(FULL, alpha, (lane & 16) | j);
                    uint2 yv = *(const uint2*)(g_rec + (size_t)sj * RECS + 2 * lane);
                    float2 f0 = __half22float2(*(__half2*)&yv.x);
                    float2 f1 = __half22float2(*(__half2*)&yv.y);
                    acc.x += a * f0.x; acc.y += a * f0.y;
                    acc.z += a * f1.x; acc.w += a * f1.y;
                }
                float got = __shfl_xor_sync(FULL, gate, 16);
                float ox = __shfl_xor_sync(FULL, acc.x, 16);
                float oy = __shfl_xor_sync(FULL, acc.y, 16);
                float oz = __shfl_xor_sync(FULL, acc.z, 16);
                float ow = __shfl_xor_sync(FULL, acc.w, 16);
                if (lane < 16) {
                    float4 gy;
                    gy.x = gate * acc.x + got * ox;
                    gy.y = gate * acc.y + got * oy;
                    gy.z = gate * acc.z + got * oz;
                    gy.w = gate * acc.w + got * ow;
                    *(float4*)&gys[(wid * 8 + q) * 64 + 4 * lane] = gy;
                }
            }
        }
        __syncthreads();  // gys visible

        // ---- fill ms (= xm + gy + bmerge) and h tile, fragment-packed fp16 -
        for (int idx = tid; idx < 64 * 64; idx += 256) {
            int nn = idx >> 6, k = idx & 63;
            int node = n0 + nn;
            float mv = 0.f, hv = 0.f;
            if (node < NNODES) {
                mv = g_xm[(size_t)node * 64 + k] + gys[nn * 64 + k] + bmerge[k];
                hv = hin[node * 64 + k];
            }
            int pi = packA_idx(nn & 15, k & 15, (nn >> 4) * 4 + (k >> 4));
            ma_h[pi] = __float2half(mv);
            ha_h[pi] = __float2half(hv);
        }
        __syncthreads();

        float rr[4][4], zz[4][4];
#pragma unroll
        for (int g = 0; g < 3; ++g) {
            float ai[4][4], ah[4][4];
#pragma unroll
            for (int nt = 0; nt < 4; ++nt)
#pragma unroll
                for (int e = 0; e < 4; ++e) { ai[nt][e] = 0.f; ah[nt][e] = 0.f; }
#pragma unroll
            for (int ks = 0; ks < 4; ++ks) {
                uint4 av = ((const uint4*)ma)[(rg * 4 + ks) * 32 + lane];
                uint4 hv4 = ((const uint4*)ha)[(rg * 4 + ks) * 32 + lane];
                int si = (g * 2 + ch) * 4 + ks;
                int sh = ((3 + g) * 2 + ch) * 4 + ks;
                uint4 wi01 = ((const uint4*)wbA)[si * 32 + lane];
                uint4 wi23 = ((const uint4*)wbB)[si * 32 + lane];
                uint4 wh01 = ((const uint4*)wbA)[sh * 32 + lane];
                uint4 wh23 = ((const uint4*)wbB)[sh * 32 + lane];
                mma_f16(ai[0], av.x, av.y, av.z, av.w, wi01.x, wi01.y);
                mma_f16(ai[1], av.x, av.y, av.z, av.w, wi01.z, wi01.w);
                mma_f16(ai[2], av.x, av.y, av.z, av.w, wi23.x, wi23.y);
                mma_f16(ai[3], av.x, av.y, av.z, av.w, wi23.z, wi23.w);
                mma_f16(ah[0], hv4.x, hv4.y, hv4.z, hv4.w, wh01.x, wh01.y);
                mma_f16(ah[1], hv4.x, hv4.y, hv4.z, hv4.w, wh01.z, wh01.w);
                mma_f16(ah[2], hv4.x, hv4.y, hv4.z, hv4.w, wh23.x, wh23.y);
                mma_f16(ah[3], hv4.x, hv4.y, hv4.z, hv4.w, wh23.z, wh23.w);
            }

            if (g == 2) __syncthreads();  // all ma reads done before nh overwrite

#pragma unroll
            for (int nt = 0; nt < 4; ++nt) {
#pragma unroll
                for (int half = 0; half < 2; ++half) {
                    int e0 = half * 2;
                    int c0 = colh + nt * 8 + (lane & 3) * 2;
                    int r = row0 + half * 8;
                    if (g == 0) {
                        rr[nt][e0]     = sigmoidf_(ai[nt][e0] + b_ih[c0] +
                                                   ah[nt][e0] + b_hh[c0]);
                        rr[nt][e0 + 1] = sigmoidf_(ai[nt][e0 + 1] + b_ih[c0 + 1] +
                                                   ah[nt][e0 + 1] + b_hh[c0 + 1]);
                    } else if (g == 1) {
                        zz[nt][e0]     = sigmoidf_(ai[nt][e0] + b_ih[64 + c0] +
                                                   ah[nt][e0] + b_hh[64 + c0]);
                        zz[nt][e0 + 1] = sigmoidf_(ai[nt][e0 + 1] + b_ih[64 + c0 + 1] +
                                                   ah[nt][e0 + 1] + b_hh[64 + c0 + 1]);
                    } else {
                        float v[2];
#pragma unroll
                        for (int q = 0; q < 2; ++q) {
                            int c = c0 + q;
                            float gi = ai[nt][e0 + q] + b_ih[128 + c];
                            float gh = ah[nt][e0 + q] + b_hh[128 + c];
                            float ng = tanhf(gi + rr[nt][e0 + q] * gh);
                            int l = ((lane >> 2) << 2) | ((c & 7) >> 1);
                            int j = (half << 1) | (((c >> 3) & 1) << 2) | (c & 1);
                            int pi = (((rg * 4 + (c >> 4)) * 32 + l) << 3) + j;
                            float hvv = __half2float(ha_h[pi]);
                            v[q] = (1.f - zz[nt][e0 + q]) * ng + zz[nt][e0 + q] * hvv;
                            ma_h[pi] = __float2half(v[q]);  // nh packed
                        }
                        int node = n0 + r;
                        if (node < NNODES)
                            *(float2*)&out[(size_t)NNODES * 64 + (size_t)node * 64 + c0] =
                                make_float2(v[0], v[1]);
                    }
                }
            }
        }
        __syncthreads();  // nh complete

        // output projection: source = nh @ Wout + bout
        float C[4][4];
#pragma unroll
        for (int nt = 0; nt < 4; ++nt)
#pragma unroll
            for (int e = 0; e < 4; ++e) C[nt][e] = 0.f;
#pragma unroll
        for (int ks = 0; ks < 4; ++ks) {
            uint4 av = ((const uint4*)ma)[(rg * 4 + ks) * 32 + lane];
            int s = (6 * 2 + ch) * 4 + ks;
            uint4 b01 = ((const uint4*)wbA)[s * 32 + lane];
            uint4 b23 = ((const uint4*)wbB)[s * 32 + lane];
            mma_f16(C[0], av.x, av.y, av.z, av.w, b01.x, b01.y);
            mma_f16(C[1], av.x, av.y, av.z, av.w, b01.z, b01.w);
            mma_f16(C[2], av.x, av.y, av.z, av.w, b23.x, b23.y);
            mma_f16(C[3], av.x, av.y, av.z, av.w, b23.z, b23.w);
        }
#pragma unroll
        for (int nt = 0; nt < 4; ++nt) {
            int c0 = colh + nt * 8 + (lane & 3) * 2;
            float ba = bout[c0], bb = bout[c0 + 1];
            if (node0 < NNODES)
                *(float2*)&out[(size_t)node0 * 64 + c0] =
                    make_float2(C[nt][0] + ba, C[nt][1] + bb);
            if (node1 < NNODES)
                *(float2*)&out[(size_t)node1 * 64 + c0] =
                    make_float2(C[nt][2] + ba, C[nt][3] + bb);
        }
    }
}

// ---------------- launch ---------------------------------------------------
extern "C" void kernel_launch(void* const* d_in, const int* in_sizes, int n_in,
                              void* d_out, int out_size) {
    const float* x    = (const float*)d_in[0];
    const float* hin  = (const float*)d_in[1];
    const int*   srcp = (const int*)d_in[2];
    const float* Wm   = (const float*)d_in[4];
    const float* bm   = (const float*)d_in[5];
    const float* Wg   = (const float*)d_in[6];
    const float* bg   = (const float*)d_in[7];
    const float* Wfc  = (const float*)d_in[8];
    const float* al   = (const float*)d_in[9];
    const float* ar   = (const float*)d_in[10];
    const float* Wmg  = (const float*)d_in[11];
    const float* bmg  = (const float*)d_in[12];
    const float* Wih  = (const float*)d_in[13];
    const float* Whh  = (const float*)d_in[14];
    const float* bih  = (const float*)d_in[15];
    const float* bhh  = (const float*)d_in[16];
    const float* Wo   = (const float*)d_in[17];
    const float* bo   = (const float*)d_in[18];
    float* out = (float*)d_out;

    cudaFuncSetAttribute(k1_node_linear, cudaFuncAttributeMaxDynamicSharedMemorySize, K1_SMEM);
    cudaFuncSetAttribute(k3_fused, cudaFuncAttributeMaxDynamicSharedMemorySize, K3_SMEM);

    k0_prep<<<257, 64>>>(Wfc, al, ar, Wmg);
    k0_pack<<<245, 256>>>(Wm, Wg, Wmg, Wih, Whh, Wo);
    k1_node_linear<<<GRID_P2, 256, K1_SMEM>>>(x, bm);
    k3_fused<<<GRID_P2, 256, K3_SMEM>>>(srcp, Wg, bg, bmg, hin, bih, bhh, bo, out);
}